// round 6
// baseline (speedup 1.0000x reference)
#include <cuda_runtime.h>
#include <cuda_fp16.h>
#include <cstdint>

// Problem dims
constexpr int Lt = 128;
constexpr int Bt = 128;
constexpr int Hd = 1024;
constexpr int Gd = 4 * Hd;       // 4096
constexpr int KA = 512;          // K of both phase-1 sub-GEMMs

// Static scratch
__device__ float g_gx_act[(size_t)Lt * Bt * Gd];     // act-side gate projections
__device__ float g_gx_inp[(size_t)Bt * Gd];          // input-side (t-invariant)
__device__ __align__(16) __half g_act_h[(size_t)Lt * Bt * KA];
__device__ __align__(16) __half g_inp_h[(size_t)Bt * KA];
__device__ __align__(16) __half g_wih_h[(size_t)Gd * 1024];
__device__ __align__(16) __half g_hbuf_h[2][Bt * Hd];
__device__ unsigned g_bar_count;
__device__ unsigned g_bar_gen;

// ---------------------------------------------------------------- helpers
__device__ __forceinline__ uint32_t h2u(__half2 v) {
    __half2_raw r = *(__half2_raw*)&v;
    return (uint32_t)r.x | ((uint32_t)r.y << 16);
}
__device__ __forceinline__ void mma16(float* c, const uint32_t* a,
                                      uint32_t b0, uint32_t b1) {
    asm volatile(
        "mma.sync.aligned.m16n8k16.row.col.f32.f16.f16.f32 "
        "{%0,%1,%2,%3},{%4,%5,%6,%7},{%8,%9},{%0,%1,%2,%3};"
        : "+f"(c[0]), "+f"(c[1]), "+f"(c[2]), "+f"(c[3])
        : "r"(a[0]), "r"(a[1]), "r"(a[2]), "r"(a[3]), "r"(b0), "r"(b1));
}
__device__ __forceinline__ void ldsm4(uint32_t& d0, uint32_t& d1,
                                      uint32_t& d2, uint32_t& d3, uint32_t a) {
    asm volatile("ldmatrix.sync.aligned.m8n8.x4.shared.b16 {%0,%1,%2,%3}, [%4];"
                 : "=r"(d0), "=r"(d1), "=r"(d2), "=r"(d3) : "r"(a));
}
__device__ __forceinline__ void cpa16(uint32_t d, const void* s) {
    asm volatile("cp.async.cg.shared.global [%0], [%1], 16;" :: "r"(d), "l"(s));
}
__device__ __forceinline__ void cpcommit() { asm volatile("cp.async.commit_group;"); }
template<int N> __device__ __forceinline__ void cpwait() {
    asm volatile("cp.async.wait_group %0;" :: "n"(N));
}
__device__ __forceinline__ uint32_t s2u(const void* p) {
    return (uint32_t)__cvta_generic_to_shared(p);
}
__device__ __forceinline__ float sigm(float x) { return 1.0f / (1.0f + expf(-x)); }

// ============================================================================
// Prep: fp16-convert act / inp / W_ih into static buffers; reset grid barrier.
// ============================================================================
__global__ void prep_kernel(const float* __restrict__ act,
                            const float* __restrict__ inp,
                            const float* __restrict__ Wih) {
    if (blockIdx.x == 0 && threadIdx.x == 0) { g_bar_count = 0; g_bar_gen = 0; }
    const size_t NW = (size_t)Gd * 1024 / 8;      // 8-elem groups
    const size_t NA = (size_t)Lt * Bt * KA / 8;
    const size_t NI = (size_t)Bt * KA / 8;
    const size_t total = NW + NA + NI;
    for (size_t i = (size_t)blockIdx.x * blockDim.x + threadIdx.x; i < total;
         i += (size_t)gridDim.x * blockDim.x) {
        const float4* s; uint4* d;
        if (i < NW)           { s = (const float4*)Wih + 2 * i;            d = (uint4*)g_wih_h + i; }
        else if (i < NW + NA) { s = (const float4*)act + 2 * (i - NW);     d = (uint4*)g_act_h + (i - NW); }
        else                  { s = (const float4*)inp + 2 * (i - NW - NA); d = (uint4*)g_inp_h + (i - NW - NA); }
        float4 v0 = s[0], v1 = s[1];
        uint4 o;
        o.x = h2u(__floats2half2_rn(v0.x, v0.y));
        o.y = h2u(__floats2half2_rn(v0.z, v0.w));
        o.z = h2u(__floats2half2_rn(v1.x, v1.y));
        o.w = h2u(__floats2half2_rn(v1.z, v1.w));
        *d = o;
    }
}

// ============================================================================
// Phase 1: fp16 m16n8k16 GEMM. BM=BN=128, BK=32, 4-stage cp.async, ldmatrix.
// (identical to R5; launched 3x this round as a controlled timing probe)
// ============================================================================
constexpr int P1_STG = 4;
constexpr int P1_STAGE_B = 2 * 128 * 32 * 2;   // A 8KB + B 8KB = 16 KB
constexpr int P1_SMEM = P1_STG * P1_STAGE_B;   // 64 KB

__global__ void __launch_bounds__(256, 2) gemm_x_h() {
    extern __shared__ char sm1[];
    const uint32_t sBase = s2u(sm1);

    const int tid = threadIdx.x, lane = tid & 31, warp = tid >> 5;
    const int wm = warp & 3, wn = warp >> 2;
    const bool isInp = (blockIdx.y == 128);
    const int bm = isInp ? 0 : blockIdx.y * 128;
    const int bn = blockIdx.x * 128;
    const __half* Ab = isInp ? g_inp_h : g_act_h + (size_t)bm * KA;
    const __half* Bb = g_wih_h + (size_t)bn * 1024 + (isInp ? 0 : 512);
    float* Cb = isInp ? g_gx_inp : g_gx_act + (size_t)bm * Gd;

    const int r = tid >> 1;              // staging row 0..127
    const int cpair = (tid & 1) * 2;     // 2 chunks of 8 halves
    const __half* aRow = Ab + (size_t)r * KA;
    const __half* bRow = Bb + (size_t)r * 1024;

    auto loadblk = [&](int kb) {
        if (kb < 16) {
            uint32_t st = sBase + (uint32_t)(kb & 3) * P1_STAGE_B;
            const __half* a = aRow + kb * 32;
            const __half* b = bRow + kb * 32;
            #pragma unroll
            for (int j = 0; j < 2; j++) {
                int c = cpair + j;
                uint32_t off = (uint32_t)(((r >> 3) * 4 + c) * 128)
                             + (uint32_t)((((r & 7) ^ c) * 16));
                cpa16(st + off, a + c * 8);
                cpa16(st + 8192 + off, b + c * 8);
            }
        }
        cpcommit();
    };

    loadblk(0); loadblk(1); loadblk(2);

    float acc[2][8][4];
    #pragma unroll
    for (int i = 0; i < 2; i++)
        #pragma unroll
        for (int j = 0; j < 8; j++)
            #pragma unroll
            for (int k = 0; k < 4; k++) acc[i][j][k] = 0.0f;

    const int g = lane >> 3;             // lane group 0..3
    const int l7 = lane & 7;

    for (int kb = 0; kb < 16; kb++) {
        cpwait<2>(); __syncthreads();
        loadblk(kb + 3);
        const uint32_t stA = sBase + (uint32_t)(kb & 3) * P1_STAGE_B;
        const uint32_t stB = stA + 8192;

        #pragma unroll
        for (int kc = 0; kc < 2; kc++) {
            uint32_t a[2][4];
            #pragma unroll
            for (int tm = 0; tm < 2; tm++) {
                int rt = wm * 4 + tm * 2 + (g & 1);
                int ct = kc * 2 + (g >> 1);
                ldsm4(a[tm][0], a[tm][1], a[tm][2], a[tm][3],
                      stA + (uint32_t)((rt * 4 + ct) * 128 + ((l7 ^ ct) * 16)));
            }
            #pragma unroll
            for (int j = 0; j < 4; j++) {
                int nt = wn * 8 + 2 * j + (g >> 1);
                int ct = kc * 2 + (g & 1);
                uint32_t b0, b1, b2, b3;
                ldsm4(b0, b1, b2, b3,
                      stB + (uint32_t)((nt * 4 + ct) * 128 + ((l7 ^ ct) * 16)));
                mma16(acc[0][2 * j],     a[0], b0, b1);
                mma16(acc[0][2 * j + 1], a[0], b2, b3);
                mma16(acc[1][2 * j],     a[1], b0, b1);
                mma16(acc[1][2 * j + 1], a[1], b2, b3);
            }
        }
    }

    // epilogue
    #pragma unroll
    for (int tm = 0; tm < 2; tm++) {
        int rr = wm * 32 + tm * 16 + (lane >> 2);
        #pragma unroll
        for (int tn = 0; tn < 8; tn++) {
            int cc = bn + wn * 64 + tn * 8 + 2 * (lane & 3);
            *(float2*)&Cb[(size_t)rr * Gd + cc] =
                make_float2(acc[tm][tn][0], acc[tm][tn][1]);
            *(float2*)&Cb[(size_t)(rr + 8) * Gd + cc] =
                make_float2(acc[tm][tn][2], acc[tm][tn][3]);
        }
    }
}

// ============================================================================
// Phase 2: persistent LSTM recurrence (identical to R5).
// ============================================================================
constexpr int NTHR = 256;
constexpr int WS_B = 32 * 1024 * 2;             // 64 KB W tiles
constexpr int HT_STAGE_B = 128 * 64 * 2;        // 16 KB per h stage
constexpr int SMEM2 = WS_B + 4 * HT_STAGE_B;    // 128 KB

__device__ __forceinline__ void gbar(unsigned target) {
    __syncthreads();
    if (threadIdx.x == 0) {
        __threadfence();
        unsigned old = atomicAdd(&g_bar_count, 1u);
        if ((old + 1u) % gridDim.x == 0u) {
            __threadfence();
            asm volatile("red.release.gpu.global.add.u32 [%0], %1;"
                         :: "l"(&g_bar_gen), "r"(1u) : "memory");
        } else {
            unsigned gg;
            do {
                asm volatile("ld.acquire.gpu.global.u32 %0, [%1];"
                             : "=r"(gg) : "l"(&g_bar_gen) : "memory");
            } while (gg < target);
        }
        __threadfence();
    }
    __syncthreads();
}

__global__ void __launch_bounds__(NTHR, 1) lstm_seq_kernel(
    const float* __restrict__ h0, const float* __restrict__ c0in,
    const float* __restrict__ Whh, const float* __restrict__ bih,
    const float* __restrict__ bhh, float* __restrict__ out, int out_size)
{
    extern __shared__ char sm2[];
    const uint32_t sW = s2u(sm2);
    const uint32_t sSt = sW + WS_B;

    const int tid = threadIdx.x, lane = tid & 31, warp = tid >> 5;
    const int cta = blockIdx.x;
    const int ub  = cta * 8;
    const int u0  = ub + 2 * (lane & 3);
    const int b0  = warp * 16 + (lane >> 2);

    // --- W_hh slice -> smem fp16, tile-native layout
    for (int i = tid; i < 32 * 128; i += NTHR) {
        int lr = i >> 7;          // 0..31
        int c  = i & 127;         // k-chunk (8 halves)
        int gate = lr >> 3, unit = lr & 7;
        const float* src = Whh + (size_t)(gate * Hd + ub + unit) * Hd + c * 8;
        float4 v0 = *(const float4*)src;
        float4 v1 = *(const float4*)(src + 4);
        uint4 o;
        o.x = h2u(__floats2half2_rn(v0.x, v0.y));
        o.y = h2u(__floats2half2_rn(v0.z, v0.w));
        o.z = h2u(__floats2half2_rn(v1.x, v1.y));
        o.w = h2u(__floats2half2_rn(v1.z, v1.w));
        uint32_t off = (uint32_t)((gate * 128 + c) * 128 + ((unit ^ (c & 7)) * 16));
        *(uint4*)(sm2 + off) = o;
    }

    // t-invariant gate term: input-projection + both biases
    float2 gxi[4][2];
    #pragma unroll
    for (int q = 0; q < 4; q++) {
        float bx = bih[q * Hd + u0]     + bhh[q * Hd + u0];
        float by = bih[q * Hd + u0 + 1] + bhh[q * Hd + u0 + 1];
        #pragma unroll
        for (int bs = 0; bs < 2; bs++) {
            int b = b0 + bs * 8;
            float2 v = *(const float2*)&g_gx_inp[(size_t)b * Gd + q * Hd + u0];
            gxi[q][bs] = make_float2(v.x + bx, v.y + by);
        }
    }

    float creg[2][2];
    #pragma unroll
    for (int bs = 0; bs < 2; bs++) {
        int b = b0 + bs * 8;
        creg[bs][0] = c0in[(size_t)b * Hd + u0];
        creg[bs][1] = c0in[(size_t)b * Hd + u0 + 1];
    }

    // initial h broadcast (each CTA writes one batch row, fp16)
    for (int i = tid; i < Hd / 2; i += NTHR) {
        float2 v = *(const float2*)&h0[(size_t)cta * Hd + 2 * i];
        *(__half2*)&g_hbuf_h[0][cta * Hd + 2 * i] = __floats2half2_rn(v.x, v.y);
    }
    gbar(1);

    // staging + ldmatrix geometry
    const int sr = tid >> 1;                 // staging row 0..127
    const int scb = (tid & 1) * 4;           // 4 chunks of 8 halves
    const int g = lane >> 3, l7 = lane & 7;

    for (int t = 0; t < Lt; t++) {
        const __half* cur = g_hbuf_h[t & 1];
        __half* nxt = g_hbuf_h[(t + 1) & 1];

        float2 gxa[4][2];
        #pragma unroll
        for (int q = 0; q < 4; q++)
            #pragma unroll
            for (int bs = 0; bs < 2; bs++) {
                int b = b0 + bs * 8;
                gxa[q][bs] = *(const float2*)
                    &g_gx_act[((size_t)t * Bt + b) * Gd + q * Hd + u0];
            }

        float acc[4][4];
        #pragma unroll
        for (int q = 0; q < 4; q++)
            #pragma unroll
            for (int k = 0; k < 4; k++) acc[q][k] = 0.0f;

        auto stage = [&](int kb) {
            if (kb < 16) {
                uint32_t st = sSt + (uint32_t)(kb & 3) * HT_STAGE_B;
                const __half* s = cur + (size_t)sr * Hd + kb * 64;
                #pragma unroll
                for (int j = 0; j < 4; j++) {
                    int c = scb + j;
                    uint32_t off = (uint32_t)(((sr >> 3) * 8 + c) * 128
                                 + (((sr & 7) ^ (c & 7)) * 16));
                    cpa16(st + off, s + c * 8);
                }
            }
            cpcommit();
        };

        stage(0); stage(1); stage(2);

        for (int kb = 0; kb < 16; kb++) {
            cpwait<2>(); __syncthreads();
            stage(kb + 3);
            const uint32_t st = sSt + (uint32_t)(kb & 3) * HT_STAGE_B;

            #pragma unroll
            for (int kc = 0; kc < 4; kc++) {
                uint32_t a[4];
                {
                    int rt = warp * 2 + (g & 1);
                    int ct = kc * 2 + (g >> 1);
                    ldsm4(a[0], a[1], a[2], a[3],
                          st + (uint32_t)((rt * 8 + ct) * 128 + ((l7 ^ ct) * 16)));
                }
                #pragma unroll
                for (int p = 0; p < 2; p++) {
                    int gate = 2 * p + (g >> 1);
                    int ctg = kb * 8 + kc * 2 + (g & 1);
                    uint32_t b0r, b1r, b2r, b3r;
                    ldsm4(b0r, b1r, b2r, b3r,
                          sW + (uint32_t)((gate * 128 + ctg) * 128
                               + ((l7 ^ (ctg & 7)) * 16)));
                    mma16(acc[2 * p],     a, b0r, b1r);
                    mma16(acc[2 * p + 1], a, b2r, b3r);
                }
            }
        }

        // cell update (all 4 gates of a unit live in this thread)
        #pragma unroll
        for (int bs = 0; bs < 2; bs++) {
            int b = b0 + bs * 8;
            float hv[2], cv[2];
            #pragma unroll
            for (int us = 0; us < 2; us++) {
                int ci = bs * 2 + us;
                float gi = acc[0][ci] + (us ? gxa[0][bs].y : gxa[0][bs].x)
                                      + (us ? gxi[0][bs].y : gxi[0][bs].x);
                float gf = acc[1][ci] + (us ? gxa[1][bs].y : gxa[1][bs].x)
                                      + (us ? gxi[1][bs].y : gxi[1][bs].x);
                float gg = acc[2][ci] + (us ? gxa[2][bs].y : gxa[2][bs].x)
                                      + (us ? gxi[2][bs].y : gxi[2][bs].x);
                float go = acc[3][ci] + (us ? gxa[3][bs].y : gxa[3][bs].x)
                                      + (us ? gxi[3][bs].y : gxi[3][bs].x);
                float cn = sigm(gf) * creg[bs][us] + sigm(gi) * tanhf(gg);
                float hn = sigm(go) * tanhf(cn);
                creg[bs][us] = cn;
                hv[us] = hn; cv[us] = cn;
            }
            size_t ob = (size_t)t * Bt * Hd + (size_t)b * Hd + u0;
            *(float2*)&out[ob] = make_float2(hv[0], hv[1]);
            if (t + 1 < Lt) {
                *(__half2*)&nxt[b * Hd + u0] = __floats2half2_rn(hv[0], hv[1]);
            } else {
                size_t HS = (size_t)Lt * Bt * Hd;
                if ((size_t)out_size >= HS + 2 * (size_t)Bt * Hd) {
                    *(float2*)&out[HS + (size_t)b * Hd + u0] =
                        make_float2(hv[0], hv[1]);
                    *(float2*)&out[HS + (size_t)Bt * Hd + (size_t)b * Hd + u0] =
                        make_float2(cv[0], cv[1]);
                }
            }
        }
        if (t + 1 < Lt) gbar((unsigned)(t + 2));
    }
}

extern "C" void kernel_launch(void* const* d_in, const int* in_sizes, int n_in,
                              void* d_out, int out_size) {
    (void)in_sizes; (void)n_in;
    const float* act = (const float*)d_in[0];
    const float* inp = (const float*)d_in[1];
    const float* h0  = (const float*)d_in[2];
    const float* c0  = (const float*)d_in[3];
    const float* Wih = (const float*)d_in[4];
    const float* Whh = (const float*)d_in[5];
    const float* bih = (const float*)d_in[6];
    const float* bhh = (const float*)d_in[7];
    float* out = (float*)d_out;

    cudaFuncSetAttribute(gemm_x_h,
                         cudaFuncAttributeMaxDynamicSharedMemorySize, P1_SMEM);
    cudaFuncSetAttribute(lstm_seq_kernel,
                         cudaFuncAttributeMaxDynamicSharedMemorySize, SMEM2);

    prep_kernel<<<1024, 256>>>(act, inp, Wih);
    // MEASUREMENT ROUND: gemm launched 3x (idempotent — pure function of the
    // prep buffers, writes identical values each time). Phase-1 duration is
    // recovered exactly as g = (T_R6 - T_R5) / 2.
    gemm_x_h<<<dim3(32, 129), 256, P1_SMEM>>>();
    gemm_x_h<<<dim3(32, 129), 256, P1_SMEM>>>();
    gemm_x_h<<<dim3(32, 129), 256, P1_SMEM>>>();
    lstm_seq_kernel<<<128, NTHR, SMEM2>>>(h0, c0, Whh, bih, bhh, out, out_size);
}

// round 7
// speedup vs baseline: 1.1460x; 1.1460x over previous
#include <cuda_runtime.h>
#include <cuda_fp16.h>
#include <cstdint>

// Problem dims
constexpr int Lt = 128;
constexpr int Bt = 128;
constexpr int Hd = 1024;
constexpr int Gd = 4 * Hd;       // 4096
constexpr int KA = 512;          // K of both phase-1 sub-GEMMs

// Static scratch
__device__ float g_gx_act[(size_t)Lt * Bt * Gd];     // act-side gate projections
__device__ float g_gx_inp[(size_t)Bt * Gd];          // input-side (t-invariant)
__device__ __align__(16) __half g_act_h[(size_t)Lt * Bt * KA];
__device__ __align__(16) __half g_inp_h[(size_t)Bt * KA];
__device__ __align__(16) __half g_wih_h[(size_t)Gd * 1024];
__device__ __align__(16) __half g_hring[4][Bt * Hd]; // 4-deep h ring buffer
__device__ unsigned g_chunk_cnt[16];                 // producer counters (64-col chunks)
__device__ unsigned g_read_done[4];                  // per-ring-slot consumer counters
__device__ unsigned g_bar_count;
__device__ unsigned g_bar_gen;

// ---------------------------------------------------------------- helpers
__device__ __forceinline__ uint32_t h2u(__half2 v) {
    __half2_raw r = *(__half2_raw*)&v;
    return (uint32_t)r.x | ((uint32_t)r.y << 16);
}
__device__ __forceinline__ void mma16(float* c, const uint32_t* a,
                                      uint32_t b0, uint32_t b1) {
    asm volatile(
        "mma.sync.aligned.m16n8k16.row.col.f32.f16.f16.f32 "
        "{%0,%1,%2,%3},{%4,%5,%6,%7},{%8,%9},{%0,%1,%2,%3};"
        : "+f"(c[0]), "+f"(c[1]), "+f"(c[2]), "+f"(c[3])
        : "r"(a[0]), "r"(a[1]), "r"(a[2]), "r"(a[3]), "r"(b0), "r"(b1));
}
__device__ __forceinline__ void ldsm4(uint32_t& d0, uint32_t& d1,
                                      uint32_t& d2, uint32_t& d3, uint32_t a) {
    asm volatile("ldmatrix.sync.aligned.m8n8.x4.shared.b16 {%0,%1,%2,%3}, [%4];"
                 : "=r"(d0), "=r"(d1), "=r"(d2), "=r"(d3) : "r"(a));
}
__device__ __forceinline__ void cpa16(uint32_t d, const void* s) {
    asm volatile("cp.async.cg.shared.global [%0], [%1], 16;" :: "r"(d), "l"(s));
}
__device__ __forceinline__ void cpcommit() { asm volatile("cp.async.commit_group;"); }
template<int N> __device__ __forceinline__ void cpwait() {
    asm volatile("cp.async.wait_group %0;" :: "n"(N));
}
__device__ __forceinline__ uint32_t s2u(const void* p) {
    return (uint32_t)__cvta_generic_to_shared(p);
}
__device__ __forceinline__ float sigm(float x) { return 1.0f / (1.0f + expf(-x)); }
__device__ __forceinline__ unsigned ldacq(const unsigned* p) {
    unsigned v;
    asm volatile("ld.acquire.gpu.global.u32 %0, [%1];" : "=r"(v) : "l"(p) : "memory");
    return v;
}
__device__ __forceinline__ void redrel(unsigned* p, unsigned v) {
    asm volatile("red.release.gpu.global.add.u32 [%0], %1;" :: "l"(p), "r"(v) : "memory");
}

// ============================================================================
// Prep: fp16-convert act / inp / W_ih; reset all sync counters.
// ============================================================================
__global__ void prep_kernel(const float* __restrict__ act,
                            const float* __restrict__ inp,
                            const float* __restrict__ Wih) {
    if (blockIdx.x == 0 && threadIdx.x == 0) {
        g_bar_count = 0; g_bar_gen = 0;
        #pragma unroll
        for (int i = 0; i < 16; i++) g_chunk_cnt[i] = 0;
        #pragma unroll
        for (int i = 0; i < 4; i++) g_read_done[i] = 0;
    }
    const size_t NW = (size_t)Gd * 1024 / 8;      // 8-elem groups
    const size_t NA = (size_t)Lt * Bt * KA / 8;
    const size_t NI = (size_t)Bt * KA / 8;
    const size_t total = NW + NA + NI;
    for (size_t i = (size_t)blockIdx.x * blockDim.x + threadIdx.x; i < total;
         i += (size_t)gridDim.x * blockDim.x) {
        const float4* s; uint4* d;
        if (i < NW)           { s = (const float4*)Wih + 2 * i;            d = (uint4*)g_wih_h + i; }
        else if (i < NW + NA) { s = (const float4*)act + 2 * (i - NW);     d = (uint4*)g_act_h + (i - NW); }
        else                  { s = (const float4*)inp + 2 * (i - NW - NA); d = (uint4*)g_inp_h + (i - NW - NA); }
        float4 v0 = s[0], v1 = s[1];
        uint4 o;
        o.x = h2u(__floats2half2_rn(v0.x, v0.y));
        o.y = h2u(__floats2half2_rn(v0.z, v0.w));
        o.z = h2u(__floats2half2_rn(v1.x, v1.y));
        o.w = h2u(__floats2half2_rn(v1.z, v1.w));
        *d = o;
    }
}

// ============================================================================
// Phase 1: fp16 m16n8k16 GEMM (unchanged from R5).
// ============================================================================
constexpr int P1_STG = 4;
constexpr int P1_STAGE_B = 2 * 128 * 32 * 2;   // A 8KB + B 8KB = 16 KB
constexpr int P1_SMEM = P1_STG * P1_STAGE_B;   // 64 KB

__global__ void __launch_bounds__(256, 2) gemm_x_h() {
    extern __shared__ char sm1[];
    const uint32_t sBase = s2u(sm1);

    const int tid = threadIdx.x, lane = tid & 31, warp = tid >> 5;
    const int wm = warp & 3, wn = warp >> 2;
    const bool isInp = (blockIdx.y == 128);
    const int bm = isInp ? 0 : blockIdx.y * 128;
    const int bn = blockIdx.x * 128;
    const __half* Ab = isInp ? g_inp_h : g_act_h + (size_t)bm * KA;
    const __half* Bb = g_wih_h + (size_t)bn * 1024 + (isInp ? 0 : 512);
    float* Cb = isInp ? g_gx_inp : g_gx_act + (size_t)bm * Gd;

    const int r = tid >> 1;
    const int cpair = (tid & 1) * 2;
    const __half* aRow = Ab + (size_t)r * KA;
    const __half* bRow = Bb + (size_t)r * 1024;

    auto loadblk = [&](int kb) {
        if (kb < 16) {
            uint32_t st = sBase + (uint32_t)(kb & 3) * P1_STAGE_B;
            const __half* a = aRow + kb * 32;
            const __half* b = bRow + kb * 32;
            #pragma unroll
            for (int j = 0; j < 2; j++) {
                int c = cpair + j;
                uint32_t off = (uint32_t)(((r >> 3) * 4 + c) * 128)
                             + (uint32_t)((((r & 7) ^ c) * 16));
                cpa16(st + off, a + c * 8);
                cpa16(st + 8192 + off, b + c * 8);
            }
        }
        cpcommit();
    };

    loadblk(0); loadblk(1); loadblk(2);

    float acc[2][8][4];
    #pragma unroll
    for (int i = 0; i < 2; i++)
        #pragma unroll
        for (int j = 0; j < 8; j++)
            #pragma unroll
            for (int k = 0; k < 4; k++) acc[i][j][k] = 0.0f;

    const int g = lane >> 3;
    const int l7 = lane & 7;

    for (int kb = 0; kb < 16; kb++) {
        cpwait<2>(); __syncthreads();
        loadblk(kb + 3);
        const uint32_t stA = sBase + (uint32_t)(kb & 3) * P1_STAGE_B;
        const uint32_t stB = stA + 8192;

        #pragma unroll
        for (int kc = 0; kc < 2; kc++) {
            uint32_t a[2][4];
            #pragma unroll
            for (int tm = 0; tm < 2; tm++) {
                int rt = wm * 4 + tm * 2 + (g & 1);
                int ct = kc * 2 + (g >> 1);
                ldsm4(a[tm][0], a[tm][1], a[tm][2], a[tm][3],
                      stA + (uint32_t)((rt * 4 + ct) * 128 + ((l7 ^ ct) * 16)));
            }
            #pragma unroll
            for (int j = 0; j < 4; j++) {
                int nt = wn * 8 + 2 * j + (g >> 1);
                int ct = kc * 2 + (g & 1);
                uint32_t b0, b1, b2, b3;
                ldsm4(b0, b1, b2, b3,
                      stB + (uint32_t)((nt * 4 + ct) * 128 + ((l7 ^ ct) * 16)));
                mma16(acc[0][2 * j],     a[0], b0, b1);
                mma16(acc[0][2 * j + 1], a[0], b2, b3);
                mma16(acc[1][2 * j],     a[1], b0, b1);
                mma16(acc[1][2 * j + 1], a[1], b2, b3);
            }
        }
    }

    #pragma unroll
    for (int tm = 0; tm < 2; tm++) {
        int rr = wm * 32 + tm * 16 + (lane >> 2);
        #pragma unroll
        for (int tn = 0; tn < 8; tn++) {
            int cc = bn + wn * 64 + tn * 8 + 2 * (lane & 3);
            *(float2*)&Cb[(size_t)rr * Gd + cc] =
                make_float2(acc[tm][tn][0], acc[tm][tn][1]);
            *(float2*)&Cb[(size_t)(rr + 8) * Gd + cc] =
                make_float2(acc[tm][tn][2], acc[tm][tn][3]);
        }
    }
}

// ============================================================================
// Phase 2: persistent LSTM recurrence, DATAFLOW-SYNCED (no per-step barrier).
// CTA j writes h units [8j,8j+8). Chunk c (64 cols, = stage kb c) is produced
// by CTAs 8c..8c+7: they release-add g_chunk_cnt[c] after their step-t store;
// consumers acquire-spin cnt[c] >= 8*t before cp.async-staging chunk c of
// step t. h lives in a 4-deep ring; per-slot read_done counters give an exact
// WAR guard (epilogue of step t waits read_done[(t+1)&3] >= 128*((t+1)/4)).
// ============================================================================
constexpr int NTHR = 256;
constexpr int WS_B = 32 * 1024 * 2;             // 64 KB W tiles
constexpr int HT_STAGE_B = 128 * 64 * 2;        // 16 KB per h stage
constexpr int SMEM2 = WS_B + 4 * HT_STAGE_B;    // 128 KB

__device__ __forceinline__ void gbar(unsigned target) {
    __syncthreads();
    if (threadIdx.x == 0) {
        __threadfence();
        unsigned old = atomicAdd(&g_bar_count, 1u);
        if ((old + 1u) % gridDim.x == 0u) {
            __threadfence();
            redrel(&g_bar_gen, 1u);
        } else {
            while (ldacq(&g_bar_gen) < target) { __nanosleep(64); }
        }
        __threadfence();
    }
    __syncthreads();
}

__global__ void __launch_bounds__(NTHR, 1) lstm_seq_kernel(
    const float* __restrict__ h0, const float* __restrict__ c0in,
    const float* __restrict__ Whh, const float* __restrict__ bih,
    const float* __restrict__ bhh, float* __restrict__ out, int out_size)
{
    extern __shared__ char sm2[];
    const uint32_t sW = s2u(sm2);
    const uint32_t sSt = sW + WS_B;

    const int tid = threadIdx.x, lane = tid & 31, warp = tid >> 5;
    const int cta = blockIdx.x;
    const int ub  = cta * 8;
    const int u0  = ub + 2 * (lane & 3);
    const int b0  = warp * 16 + (lane >> 2);

    // --- W_hh slice -> smem fp16, tile-native layout
    for (int i = tid; i < 32 * 128; i += NTHR) {
        int lr = i >> 7;
        int c  = i & 127;
        int gate = lr >> 3, unit = lr & 7;
        const float* src = Whh + (size_t)(gate * Hd + ub + unit) * Hd + c * 8;
        float4 v0 = *(const float4*)src;
        float4 v1 = *(const float4*)(src + 4);
        uint4 o;
        o.x = h2u(__floats2half2_rn(v0.x, v0.y));
        o.y = h2u(__floats2half2_rn(v0.z, v0.w));
        o.z = h2u(__floats2half2_rn(v1.x, v1.y));
        o.w = h2u(__floats2half2_rn(v1.z, v1.w));
        uint32_t off = (uint32_t)((gate * 128 + c) * 128 + ((unit ^ (c & 7)) * 16));
        *(uint4*)(sm2 + off) = o;
    }

    // t-invariant gate term: input-projection + both biases
    float2 gxi[4][2];
    #pragma unroll
    for (int q = 0; q < 4; q++) {
        float bx = bih[q * Hd + u0]     + bhh[q * Hd + u0];
        float by = bih[q * Hd + u0 + 1] + bhh[q * Hd + u0 + 1];
        #pragma unroll
        for (int bs = 0; bs < 2; bs++) {
            int b = b0 + bs * 8;
            float2 v = *(const float2*)&g_gx_inp[(size_t)b * Gd + q * Hd + u0];
            gxi[q][bs] = make_float2(v.x + bx, v.y + by);
        }
    }

    float creg[2][2];
    #pragma unroll
    for (int bs = 0; bs < 2; bs++) {
        int b = b0 + bs * 8;
        creg[bs][0] = c0in[(size_t)b * Hd + u0];
        creg[bs][1] = c0in[(size_t)b * Hd + u0 + 1];
    }

    // initial h -> ring slot 0 (each CTA writes one batch row, fp16)
    for (int i = tid; i < Hd / 2; i += NTHR) {
        float2 v = *(const float2*)&h0[(size_t)cta * Hd + 2 * i];
        *(__half2*)&g_hring[0][cta * Hd + 2 * i] = __floats2half2_rn(v.x, v.y);
    }
    gbar(1);   // one-time: ring[0] + counters visible everywhere

    // staging + ldmatrix geometry
    const int sr = tid >> 1;
    const int scb = (tid & 1) * 4;
    const int g = lane >> 3, l7 = lane & 7;
    const int mychunk = cta >> 3;            // chunk this CTA produces

    for (int t = 0; t < Lt; t++) {
        const __half* cur = g_hring[t & 3];
        __half* nxt = g_hring[(t + 1) & 3];

        float2 gxa[4][2];
        #pragma unroll
        for (int q = 0; q < 4; q++)
            #pragma unroll
            for (int bs = 0; bs < 2; bs++) {
                int b = b0 + bs * 8;
                gxa[q][bs] = *(const float2*)
                    &g_gx_act[((size_t)t * Bt + b) * Gd + q * Hd + u0];
            }

        float acc[4][4];
        #pragma unroll
        for (int q = 0; q < 4; q++)
            #pragma unroll
            for (int k = 0; k < 4; k++) acc[q][k] = 0.0f;

        auto stage = [&](int kb) {
            if (kb < 16) {
                if (t > 0) {                      // chunk kb ready for step t?
                    unsigned need = 8u * (unsigned)t;
                    while (ldacq(&g_chunk_cnt[kb]) < need) { __nanosleep(64); }
                }
                uint32_t st = sSt + (uint32_t)(kb & 3) * HT_STAGE_B;
                const __half* s = cur + (size_t)sr * Hd + kb * 64;
                #pragma unroll
                for (int j = 0; j < 4; j++) {
                    int c = scb + j;
                    uint32_t off = (uint32_t)(((sr >> 3) * 8 + c) * 128
                                 + (((sr & 7) ^ (c & 7)) * 16));
                    cpa16(st + off, s + c * 8);
                }
            }
            cpcommit();
        };

        stage(0); stage(1); stage(2);

        for (int kb = 0; kb < 16; kb++) {
            cpwait<2>(); __syncthreads();
            stage(kb + 3);
            const uint32_t st = sSt + (uint32_t)(kb & 3) * HT_STAGE_B;

            #pragma unroll
            for (int kc = 0; kc < 4; kc++) {
                uint32_t a[4];
                {
                    int rt = warp * 2 + (g & 1);
                    int ct = kc * 2 + (g >> 1);
                    ldsm4(a[0], a[1], a[2], a[3],
                          st + (uint32_t)((rt * 8 + ct) * 128 + ((l7 ^ ct) * 16)));
                }
                #pragma unroll
                for (int p = 0; p < 2; p++) {
                    int gate = 2 * p + (g >> 1);
                    int ctg = kb * 8 + kc * 2 + (g & 1);
                    uint32_t b0r, b1r, b2r, b3r;
                    ldsm4(b0r, b1r, b2r, b3r,
                          sW + (uint32_t)((gate * 128 + ctg) * 128
                               + ((l7 ^ (ctg & 7)) * 16)));
                    mma16(acc[2 * p],     a, b0r, b1r);
                    mma16(acc[2 * p + 1], a, b2r, b3r);
                }
            }
        }

        // all of this CTA's ring reads for step t are complete -> signal
        cpwait<0>(); __syncthreads();
        if (tid == 0) redrel(&g_read_done[t & 3], 1);

        // WAR guard: ring slot (t+1)&3 must have been fully read at step t-3
        if (t + 1 < Lt && t >= 3) {
            if (tid == 0) {
                unsigned need = 128u * ((unsigned)(t + 1) >> 2);
                while (ldacq(&g_read_done[(t + 1) & 3]) < need) { __nanosleep(64); }
            }
            __syncthreads();
        }

        // cell update (all 4 gates of a unit live in this thread)
        #pragma unroll
        for (int bs = 0; bs < 2; bs++) {
            int b = b0 + bs * 8;
            float hv[2], cv[2];
            #pragma unroll
            for (int us = 0; us < 2; us++) {
                int ci = bs * 2 + us;
                float gi = acc[0][ci] + (us ? gxa[0][bs].y : gxa[0][bs].x)
                                      + (us ? gxi[0][bs].y : gxi[0][bs].x);
                float gf = acc[1][ci] + (us ? gxa[1][bs].y : gxa[1][bs].x)
                                      + (us ? gxi[1][bs].y : gxi[1][bs].x);
                float gg = acc[2][ci] + (us ? gxa[2][bs].y : gxa[2][bs].x)
                                      + (us ? gxi[2][bs].y : gxi[2][bs].x);
                float go = acc[3][ci] + (us ? gxa[3][bs].y : gxa[3][bs].x)
                                      + (us ? gxi[3][bs].y : gxi[3][bs].x);
                float cn = sigm(gf) * creg[bs][us] + sigm(gi) * tanhf(gg);
                float hn = sigm(go) * tanhf(cn);
                creg[bs][us] = cn;
                hv[us] = hn; cv[us] = cn;
            }
            size_t ob = (size_t)t * Bt * Hd + (size_t)b * Hd + u0;
            *(float2*)&out[ob] = make_float2(hv[0], hv[1]);
            if (t + 1 < Lt) {
                *(__half2*)&nxt[b * Hd + u0] = __floats2half2_rn(hv[0], hv[1]);
            } else {
                size_t HS = (size_t)Lt * Bt * Hd;
                if ((size_t)out_size >= HS + 2 * (size_t)Bt * Hd) {
                    *(float2*)&out[HS + (size_t)b * Hd + u0] =
                        make_float2(hv[0], hv[1]);
                    *(float2*)&out[HS + (size_t)Bt * Hd + (size_t)b * Hd + u0] =
                        make_float2(cv[0], cv[1]);
                }
            }
        }

        // publish this CTA's h slice for step t+1
        if (t + 1 < Lt) {
            __syncthreads();                 // all 256 threads' h stores issued
            if (tid == 0) {
                __threadfence();             // make them gpu-visible
                redrel(&g_chunk_cnt[mychunk], 1u);
            }
        }
    }
}

extern "C" void kernel_launch(void* const* d_in, const int* in_sizes, int n_in,
                              void* d_out, int out_size) {
    (void)in_sizes; (void)n_in;
    const float* act = (const float*)d_in[0];
    const float* inp = (const float*)d_in[1];
    const float* h0  = (const float*)d_in[2];
    const float* c0  = (const float*)d_in[3];
    const float* Wih = (const float*)d_in[4];
    const float* Whh = (const float*)d_in[5];
    const float* bih = (const float*)d_in[6];
    const float* bhh = (const float*)d_in[7];
    float* out = (float*)d_out;

    cudaFuncSetAttribute(gemm_x_h,
                         cudaFuncAttributeMaxDynamicSharedMemorySize, P1_SMEM);
    cudaFuncSetAttribute(lstm_seq_kernel,
                         cudaFuncAttributeMaxDynamicSharedMemorySize, SMEM2);

    prep_kernel<<<1024, 256>>>(act, inp, Wih);
    gemm_x_h<<<dim3(32, 129), 256, P1_SMEM>>>();
    lstm_seq_kernel<<<128, NTHR, SMEM2>>>(h0, c0, Whh, bih, bhh, out, out_size);
}

// round 8
// speedup vs baseline: 1.2235x; 1.0677x over previous
#include <cuda_runtime.h>
#include <cuda_fp16.h>
#include <cstdint>

// Problem dims
constexpr int Lt = 128;
constexpr int Bt = 128;
constexpr int Hd = 1024;
constexpr int Gd = 4 * Hd;       // 4096
constexpr int KA = 512;          // K of both phase-1 sub-GEMMs

// Static scratch
__device__ float g_gx_act[(size_t)Lt * Bt * Gd];     // act-side gate projections
__device__ float g_gx_inp[(size_t)Bt * Gd];          // input-side (t-invariant)
__device__ __align__(16) __half g_act_h[(size_t)Lt * Bt * KA];
__device__ __align__(16) __half g_inp_h[(size_t)Bt * KA];
__device__ __align__(16) __half g_wih_h[(size_t)Gd * 1024];
__device__ __align__(16) __half g_hbuf_h[2][Bt * Hd];
__device__ unsigned g_bar_count;
__device__ unsigned g_bar_gen;

// ---------------------------------------------------------------- helpers
__device__ __forceinline__ uint32_t h2u(__half2 v) {
    __half2_raw r = *(__half2_raw*)&v;
    return (uint32_t)r.x | ((uint32_t)r.y << 16);
}
__device__ __forceinline__ void mma16(float* c, const uint32_t* a,
                                      uint32_t b0, uint32_t b1) {
    asm volatile(
        "mma.sync.aligned.m16n8k16.row.col.f32.f16.f16.f32 "
        "{%0,%1,%2,%3},{%4,%5,%6,%7},{%8,%9},{%0,%1,%2,%3};"
        : "+f"(c[0]), "+f"(c[1]), "+f"(c[2]), "+f"(c[3])
        : "r"(a[0]), "r"(a[1]), "r"(a[2]), "r"(a[3]), "r"(b0), "r"(b1));
}
__device__ __forceinline__ void ldsm4(uint32_t& d0, uint32_t& d1,
                                      uint32_t& d2, uint32_t& d3, uint32_t a) {
    asm volatile("ldmatrix.sync.aligned.m8n8.x4.shared.b16 {%0,%1,%2,%3}, [%4];"
                 : "=r"(d0), "=r"(d1), "=r"(d2), "=r"(d3) : "r"(a));
}
__device__ __forceinline__ void cpa16(uint32_t d, const void* s) {
    asm volatile("cp.async.cg.shared.global [%0], [%1], 16;" :: "r"(d), "l"(s));
}
__device__ __forceinline__ void cpcommit() { asm volatile("cp.async.commit_group;"); }
template<int N> __device__ __forceinline__ void cpwait() {
    asm volatile("cp.async.wait_group %0;" :: "n"(N));
}
__device__ __forceinline__ uint32_t s2u(const void* p) {
    return (uint32_t)__cvta_generic_to_shared(p);
}
__device__ __forceinline__ float sigm(float x) { return 1.0f / (1.0f + expf(-x)); }
__device__ __forceinline__ unsigned ldacq(const unsigned* p) {
    unsigned v;
    asm volatile("ld.acquire.gpu.global.u32 %0, [%1];" : "=r"(v) : "l"(p) : "memory");
    return v;
}
__device__ __forceinline__ void redrel(unsigned* p, unsigned v) {
    asm volatile("red.release.gpu.global.add.u32 [%0], %1;" :: "l"(p), "r"(v) : "memory");
}

// ============================================================================
// Prep: fp16-convert act / inp / W_ih; reset sync counters.
// ============================================================================
__global__ void prep_kernel(const float* __restrict__ act,
                            const float* __restrict__ inp,
                            const float* __restrict__ Wih) {
    if (blockIdx.x == 0 && threadIdx.x == 0) { g_bar_count = 0; g_bar_gen = 0; }
    const size_t NW = (size_t)Gd * 1024 / 8;      // 8-elem groups
    const size_t NA = (size_t)Lt * Bt * KA / 8;
    const size_t NI = (size_t)Bt * KA / 8;
    const size_t total = NW + NA + NI;
    for (size_t i = (size_t)blockIdx.x * blockDim.x + threadIdx.x; i < total;
         i += (size_t)gridDim.x * blockDim.x) {
        const float4* s; uint4* d;
        if (i < NW)           { s = (const float4*)Wih + 2 * i;            d = (uint4*)g_wih_h + i; }
        else if (i < NW + NA) { s = (const float4*)act + 2 * (i - NW);     d = (uint4*)g_act_h + (i - NW); }
        else                  { s = (const float4*)inp + 2 * (i - NW - NA); d = (uint4*)g_inp_h + (i - NW - NA); }
        float4 v0 = s[0], v1 = s[1];
        uint4 o;
        o.x = h2u(__floats2half2_rn(v0.x, v0.y));
        o.y = h2u(__floats2half2_rn(v0.z, v0.w));
        o.z = h2u(__floats2half2_rn(v1.x, v1.y));
        o.w = h2u(__floats2half2_rn(v1.z, v1.w));
        *d = o;
    }
}

// ============================================================================
// Phase 1: fp16 m16n8k16 GEMM (unchanged; 355 us measured).
// ============================================================================
constexpr int P1_STG = 4;
constexpr int P1_STAGE_B = 2 * 128 * 32 * 2;   // A 8KB + B 8KB = 16 KB
constexpr int P1_SMEM = P1_STG * P1_STAGE_B;   // 64 KB

__global__ void __launch_bounds__(256, 2) gemm_x_h() {
    extern __shared__ char sm1[];
    const uint32_t sBase = s2u(sm1);

    const int tid = threadIdx.x, lane = tid & 31, warp = tid >> 5;
    const int wm = warp & 3, wn = warp >> 2;
    const bool isInp = (blockIdx.y == 128);
    const int bm = isInp ? 0 : blockIdx.y * 128;
    const int bn = blockIdx.x * 128;
    const __half* Ab = isInp ? g_inp_h : g_act_h + (size_t)bm * KA;
    const __half* Bb = g_wih_h + (size_t)bn * 1024 + (isInp ? 0 : 512);
    float* Cb = isInp ? g_gx_inp : g_gx_act + (size_t)bm * Gd;

    const int r = tid >> 1;
    const int cpair = (tid & 1) * 2;
    const __half* aRow = Ab + (size_t)r * KA;
    const __half* bRow = Bb + (size_t)r * 1024;

    auto loadblk = [&](int kb) {
        if (kb < 16) {
            uint32_t st = sBase + (uint32_t)(kb & 3) * P1_STAGE_B;
            const __half* a = aRow + kb * 32;
            const __half* b = bRow + kb * 32;
            #pragma unroll
            for (int j = 0; j < 2; j++) {
                int c = cpair + j;
                uint32_t off = (uint32_t)(((r >> 3) * 4 + c) * 128)
                             + (uint32_t)((((r & 7) ^ c) * 16));
                cpa16(st + off, a + c * 8);
                cpa16(st + 8192 + off, b + c * 8);
            }
        }
        cpcommit();
    };

    loadblk(0); loadblk(1); loadblk(2);

    float acc[2][8][4];
    #pragma unroll
    for (int i = 0; i < 2; i++)
        #pragma unroll
        for (int j = 0; j < 8; j++)
            #pragma unroll
            for (int k = 0; k < 4; k++) acc[i][j][k] = 0.0f;

    const int g = lane >> 3;
    const int l7 = lane & 7;

    for (int kb = 0; kb < 16; kb++) {
        cpwait<2>(); __syncthreads();
        loadblk(kb + 3);
        const uint32_t stA = sBase + (uint32_t)(kb & 3) * P1_STAGE_B;
        const uint32_t stB = stA + 8192;

        #pragma unroll
        for (int kc = 0; kc < 2; kc++) {
            uint32_t a[2][4];
            #pragma unroll
            for (int tm = 0; tm < 2; tm++) {
                int rt = wm * 4 + tm * 2 + (g & 1);
                int ct = kc * 2 + (g >> 1);
                ldsm4(a[tm][0], a[tm][1], a[tm][2], a[tm][3],
                      stA + (uint32_t)((rt * 4 + ct) * 128 + ((l7 ^ ct) * 16)));
            }
            #pragma unroll
            for (int j = 0; j < 4; j++) {
                int nt = wn * 8 + 2 * j + (g >> 1);
                int ct = kc * 2 + (g & 1);
                uint32_t b0, b1, b2, b3;
                ldsm4(b0, b1, b2, b3,
                      stB + (uint32_t)((nt * 4 + ct) * 128 + ((l7 ^ ct) * 16)));
                mma16(acc[0][2 * j],     a[0], b0, b1);
                mma16(acc[0][2 * j + 1], a[0], b2, b3);
                mma16(acc[1][2 * j],     a[1], b0, b1);
                mma16(acc[1][2 * j + 1], a[1], b2, b3);
            }
        }
    }

    #pragma unroll
    for (int tm = 0; tm < 2; tm++) {
        int rr = wm * 32 + tm * 16 + (lane >> 2);
        #pragma unroll
        for (int tn = 0; tn < 8; tn++) {
            int cc = bn + wn * 64 + tn * 8 + 2 * (lane & 3);
            *(float2*)&Cb[(size_t)rr * Gd + cc] =
                make_float2(acc[tm][tn][0], acc[tm][tn][1]);
            *(float2*)&Cb[(size_t)(rr + 8) * Gd + cc] =
                make_float2(acc[tm][tn][2], acc[tm][tn][3]);
        }
    }
}

// ============================================================================
// Phase 2: persistent LSTM recurrence. 512 threads = 8 M-warps x 2 K-halves.
// Warp (mw,kw) computes all N=32 gate-cols for batches [mw*16,mw*16+16) over
// K-half kw*512..  kw=1 partials reduced via smem; cell update (kw=0 warps)
// identical to R5. Staging: 8 iterations x 2 chunks (32KB/group, 3 in flight).
// Sync: R5 gbar (single atomic + single-line poll, no nanosleep).
// ============================================================================
constexpr int NTHR2 = 512;
constexpr int WS_B = 32 * 1024 * 2;             // 64 KB W tiles
constexpr int SLOT_B = 128 * 64 * 2;            // 16 KB per h chunk slot
constexpr int SMEM2 = WS_B + 8 * SLOT_B;        // 192 KB

__device__ __forceinline__ void gbar(unsigned target) {
    __syncthreads();
    if (threadIdx.x == 0) {
        __threadfence();
        unsigned old = atomicAdd(&g_bar_count, 1u);
        if ((old + 1u) % gridDim.x == 0u) {
            __threadfence();
            redrel(&g_bar_gen, 1u);
        } else {
            while (ldacq(&g_bar_gen) < target) { }
        }
        __threadfence();
    }
    __syncthreads();
}

__global__ void __launch_bounds__(NTHR2, 1) lstm_seq_kernel(
    const float* __restrict__ h0, const float* __restrict__ c0in,
    const float* __restrict__ Whh, const float* __restrict__ bih,
    const float* __restrict__ bhh, float* __restrict__ out, int out_size)
{
    extern __shared__ char sm2[];
    const uint32_t sW = s2u(sm2);
    const uint32_t sSt = sW + WS_B;
    float* red = (float*)(sm2 + WS_B);          // 16 KB, reused post-staging

    const int tid = threadIdx.x, lane = tid & 31, warp = tid >> 5;
    const int mw = warp & 7, kw = warp >> 3;
    const int cta = blockIdx.x;
    const int ub  = cta * 8;
    const int u0  = ub + 2 * (lane & 3);
    const int b0  = mw * 16 + (lane >> 2);

    // --- W_hh slice -> smem fp16, tile-native layout
    for (int i = tid; i < 32 * 128; i += NTHR2) {
        int lr = i >> 7;
        int c  = i & 127;
        int gate = lr >> 3, unit = lr & 7;
        const float* src = Whh + (size_t)(gate * Hd + ub + unit) * Hd + c * 8;
        float4 v0 = *(const float4*)src;
        float4 v1 = *(const float4*)(src + 4);
        uint4 o;
        o.x = h2u(__floats2half2_rn(v0.x, v0.y));
        o.y = h2u(__floats2half2_rn(v0.z, v0.w));
        o.z = h2u(__floats2half2_rn(v1.x, v1.y));
        o.w = h2u(__floats2half2_rn(v1.z, v1.w));
        uint32_t off = (uint32_t)((gate * 128 + c) * 128 + ((unit ^ (c & 7)) * 16));
        *(uint4*)(sm2 + off) = o;
    }

    // t-invariant gate term + c state (kw=0 warps only)
    float2 gxi[4][2];
    float creg[2][2];
    if (kw == 0) {
        #pragma unroll
        for (int q = 0; q < 4; q++) {
            float bx = bih[q * Hd + u0]     + bhh[q * Hd + u0];
            float by = bih[q * Hd + u0 + 1] + bhh[q * Hd + u0 + 1];
            #pragma unroll
            for (int bs = 0; bs < 2; bs++) {
                int b = b0 + bs * 8;
                float2 v = *(const float2*)&g_gx_inp[(size_t)b * Gd + q * Hd + u0];
                gxi[q][bs] = make_float2(v.x + bx, v.y + by);
            }
        }
        #pragma unroll
        for (int bs = 0; bs < 2; bs++) {
            int b = b0 + bs * 8;
            creg[bs][0] = c0in[(size_t)b * Hd + u0];
            creg[bs][1] = c0in[(size_t)b * Hd + u0 + 1];
        }
    }

    // initial h (fp16) -> buffer 0
    for (int i = tid; i < Hd / 2; i += NTHR2) {
        float2 v = *(const float2*)&h0[(size_t)cta * Hd + 2 * i];
        *(__half2*)&g_hbuf_h[0][cta * Hd + 2 * i] = __floats2half2_rn(v.x, v.y);
    }
    gbar(1);

    // staging mapping: 512 threads stage 2 chunks (32 KB) per iteration
    const int sh = tid >> 8;                 // 0: kw0 chunk, 1: kw1 chunk
    const int tt = tid & 255;
    const int sr = tt >> 1;                  // staging row 0..127
    const int scb = (tt & 1) * 4;            // 4 chunks of 8 halves
    const int g = lane >> 3, l7 = lane & 7;

    for (int t = 0; t < Lt; t++) {
        const __half* cur = g_hbuf_h[t & 1];
        __half* nxt = g_hbuf_h[(t + 1) & 1];

        float2 gxa[4][2];
        if (kw == 0) {
            #pragma unroll
            for (int q = 0; q < 4; q++)
                #pragma unroll
                for (int bs = 0; bs < 2; bs++) {
                    int b = b0 + bs * 8;
                    gxa[q][bs] = *(const float2*)
                        &g_gx_act[((size_t)t * Bt + b) * Gd + q * Hd + u0];
                }
        }

        float acc[4][4];
        #pragma unroll
        for (int q = 0; q < 4; q++)
            #pragma unroll
            for (int k = 0; k < 4; k++) acc[q][k] = 0.0f;

        auto stage = [&](int i) {
            if (i < 8) {
                int chunk = i + 8 * sh;
                uint32_t st = sSt + (uint32_t)((i & 3) + 4 * sh) * SLOT_B;
                const __half* s = cur + (size_t)sr * Hd + chunk * 64;
                #pragma unroll
                for (int j = 0; j < 4; j++) {
                    int c = scb + j;
                    uint32_t off = (uint32_t)(((sr >> 3) * 8 + c) * 128
                                 + (((sr & 7) ^ (c & 7)) * 16));
                    cpa16(st + off, s + c * 8);
                }
            }
            cpcommit();
        };

        stage(0); stage(1); stage(2);

        for (int i = 0; i < 8; i++) {
            cpwait<2>(); __syncthreads();
            stage(i + 3);
            const uint32_t st = sSt + (uint32_t)((i & 3) + 4 * kw) * SLOT_B;
            const int kbg = i + 8 * kw;     // global 64-col chunk index

            #pragma unroll
            for (int kc = 0; kc < 4; kc++) {
                uint32_t a[4];
                {
                    int rt = mw * 2 + (g & 1);
                    int ct = kc * 2 + (g >> 1);
                    ldsm4(a[0], a[1], a[2], a[3],
                          st + (uint32_t)((rt * 8 + ct) * 128 + ((l7 ^ ct) * 16)));
                }
                #pragma unroll
                for (int p = 0; p < 2; p++) {
                    int gate = 2 * p + (g >> 1);
                    int ctg = kbg * 8 + kc * 2 + (g & 1);
                    uint32_t b0r, b1r, b2r, b3r;
                    ldsm4(b0r, b1r, b2r, b3r,
                          sW + (uint32_t)((gate * 128 + ctg) * 128
                               + ((l7 ^ (ctg & 7)) * 16)));
                    mma16(acc[2 * p],     a, b0r, b1r);
                    mma16(acc[2 * p + 1], a, b2r, b3r);
                }
            }
        }
        cpwait<0>(); __syncthreads();

        // K-half reduction: kw=1 stores partials ([q][k][thread], conflict-free)
        if (kw == 1) {
            #pragma unroll
            for (int q = 0; q < 4; q++)
                #pragma unroll
                for (int k = 0; k < 4; k++)
                    red[(q * 4 + k) * 256 + mw * 32 + lane] = acc[q][k];
        }
        __syncthreads();

        if (kw == 0) {
            #pragma unroll
            for (int q = 0; q < 4; q++)
                #pragma unroll
                for (int k = 0; k < 4; k++)
                    acc[q][k] += red[(q * 4 + k) * 256 + mw * 32 + lane];

            // cell update (all 4 gates of a unit live in this thread)
            #pragma unroll
            for (int bs = 0; bs < 2; bs++) {
                int b = b0 + bs * 8;
                float hv[2], cv[2];
                #pragma unroll
                for (int us = 0; us < 2; us++) {
                    int ci = bs * 2 + us;
                    float gi = acc[0][ci] + (us ? gxa[0][bs].y : gxa[0][bs].x)
                                          + (us ? gxi[0][bs].y : gxi[0][bs].x);
                    float gf = acc[1][ci] + (us ? gxa[1][bs].y : gxa[1][bs].x)
                                          + (us ? gxi[1][bs].y : gxi[1][bs].x);
                    float gg = acc[2][ci] + (us ? gxa[2][bs].y : gxa[2][bs].x)
                                          + (us ? gxi[2][bs].y : gxi[2][bs].x);
                    float go = acc[3][ci] + (us ? gxa[3][bs].y : gxa[3][bs].x)
                                          + (us ? gxi[3][bs].y : gxi[3][bs].x);
                    float cn = sigm(gf) * creg[bs][us] + sigm(gi) * tanhf(gg);
                    float hn = sigm(go) * tanhf(cn);
                    creg[bs][us] = cn;
                    hv[us] = hn; cv[us] = cn;
                }
                size_t ob = (size_t)t * Bt * Hd + (size_t)b * Hd + u0;
                *(float2*)&out[ob] = make_float2(hv[0], hv[1]);
                if (t + 1 < Lt) {
                    *(__half2*)&nxt[b * Hd + u0] = __floats2half2_rn(hv[0], hv[1]);
                } else {
                    size_t HS = (size_t)Lt * Bt * Hd;
                    if ((size_t)out_size >= HS + 2 * (size_t)Bt * Hd) {
                        *(float2*)&out[HS + (size_t)b * Hd + u0] =
                            make_float2(hv[0], hv[1]);
                        *(float2*)&out[HS + (size_t)Bt * Hd + (size_t)b * Hd + u0] =
                            make_float2(cv[0], cv[1]);
                    }
                }
            }
        }
        if (t + 1 < Lt) gbar((unsigned)(t + 2));
    }
}

extern "C" void kernel_launch(void* const* d_in, const int* in_sizes, int n_in,
                              void* d_out, int out_size) {
    (void)in_sizes; (void)n_in;
    const float* act = (const float*)d_in[0];
    const float* inp = (const float*)d_in[1];
    const float* h0  = (const float*)d_in[2];
    const float* c0  = (const float*)d_in[3];
    const float* Wih = (const float*)d_in[4];
    const float* Whh = (const float*)d_in[5];
    const float* bih = (const float*)d_in[6];
    const float* bhh = (const float*)d_in[7];
    float* out = (float*)d_out;

    cudaFuncSetAttribute(gemm_x_h,
                         cudaFuncAttributeMaxDynamicSharedMemorySize, P1_SMEM);
    cudaFuncSetAttribute(lstm_seq_kernel,
                         cudaFuncAttributeMaxDynamicSharedMemorySize, SMEM2);

    prep_kernel<<<1024, 256>>>(act, inp, Wih);
    gemm_x_h<<<dim3(32, 129), 256, P1_SMEM>>>();
    lstm_seq_kernel<<<128, NTHR2, SMEM2>>>(h0, c0, Whh, bih, bhh, out, out_size);
}

// round 9
// speedup vs baseline: 1.2342x; 1.0087x over previous
#include <cuda_runtime.h>
#include <cuda_fp16.h>
#include <cstdint>

// Problem dims
constexpr int Lt = 128;
constexpr int Bt = 128;
constexpr int Hd = 1024;
constexpr int Gd = 4 * Hd;       // 4096
constexpr int KA = 512;          // K of both phase-1 sub-GEMMs

// Static scratch
__device__ float g_gx_act[(size_t)Lt * Bt * Gd];     // act-side gate projections
__device__ float g_gx_inp[(size_t)Bt * Gd];          // input-side (t-invariant)
__device__ __align__(16) __half g_act_h[(size_t)Lt * Bt * KA];
__device__ __align__(16) __half g_inp_h[(size_t)Bt * KA];
__device__ __align__(16) __half g_wih_h[(size_t)Gd * 1024];
__device__ __align__(16) __half g_hbuf_h[2][Bt * Hd];
__device__ unsigned g_bar_count;
__device__ unsigned g_bar_gen;

// ---------------------------------------------------------------- helpers
__device__ __forceinline__ uint32_t h2u(__half2 v) {
    __half2_raw r = *(__half2_raw*)&v;
    return (uint32_t)r.x | ((uint32_t)r.y << 16);
}
__device__ __forceinline__ void mma16(float* c, const uint32_t* a,
                                      uint32_t b0, uint32_t b1) {
    asm volatile(
        "mma.sync.aligned.m16n8k16.row.col.f32.f16.f16.f32 "
        "{%0,%1,%2,%3},{%4,%5,%6,%7},{%8,%9},{%0,%1,%2,%3};"
        : "+f"(c[0]), "+f"(c[1]), "+f"(c[2]), "+f"(c[3])
        : "r"(a[0]), "r"(a[1]), "r"(a[2]), "r"(a[3]), "r"(b0), "r"(b1));
}
__device__ __forceinline__ void ldsm4(uint32_t& d0, uint32_t& d1,
                                      uint32_t& d2, uint32_t& d3, uint32_t a) {
    asm volatile("ldmatrix.sync.aligned.m8n8.x4.shared.b16 {%0,%1,%2,%3}, [%4];"
                 : "=r"(d0), "=r"(d1), "=r"(d2), "=r"(d3) : "r"(a));
}
__device__ __forceinline__ void cpa16(uint32_t d, const void* s) {
    asm volatile("cp.async.cg.shared.global [%0], [%1], 16;" :: "r"(d), "l"(s));
}
__device__ __forceinline__ void cpcommit() { asm volatile("cp.async.commit_group;"); }
template<int N> __device__ __forceinline__ void cpwait() {
    asm volatile("cp.async.wait_group %0;" :: "n"(N));
}
__device__ __forceinline__ uint32_t s2u(const void* p) {
    return (uint32_t)__cvta_generic_to_shared(p);
}
__device__ __forceinline__ float sigm(float x) { return 1.0f / (1.0f + expf(-x)); }
__device__ __forceinline__ unsigned ldacq(const unsigned* p) {
    unsigned v;
    asm volatile("ld.acquire.gpu.global.u32 %0, [%1];" : "=r"(v) : "l"(p) : "memory");
    return v;
}
__device__ __forceinline__ void redrel(unsigned* p, unsigned v) {
    asm volatile("red.release.gpu.global.add.u32 [%0], %1;" :: "l"(p), "r"(v) : "memory");
}

// ============================================================================
// Prep: fp16-convert act / inp / W_ih; reset sync counters.
// ============================================================================
__global__ void prep_kernel(const float* __restrict__ act,
                            const float* __restrict__ inp,
                            const float* __restrict__ Wih) {
    if (blockIdx.x == 0 && threadIdx.x == 0) { g_bar_count = 0; g_bar_gen = 0; }
    const size_t NW = (size_t)Gd * 1024 / 8;      // 8-elem groups
    const size_t NA = (size_t)Lt * Bt * KA / 8;
    const size_t NI = (size_t)Bt * KA / 8;
    const size_t total = NW + NA + NI;
    for (size_t i = (size_t)blockIdx.x * blockDim.x + threadIdx.x; i < total;
         i += (size_t)gridDim.x * blockDim.x) {
        const float4* s; uint4* d;
        if (i < NW)           { s = (const float4*)Wih + 2 * i;            d = (uint4*)g_wih_h + i; }
        else if (i < NW + NA) { s = (const float4*)act + 2 * (i - NW);     d = (uint4*)g_act_h + (i - NW); }
        else                  { s = (const float4*)inp + 2 * (i - NW - NA); d = (uint4*)g_inp_h + (i - NW - NA); }
        float4 v0 = s[0], v1 = s[1];
        uint4 o;
        o.x = h2u(__floats2half2_rn(v0.x, v0.y));
        o.y = h2u(__floats2half2_rn(v0.z, v0.w));
        o.z = h2u(__floats2half2_rn(v1.x, v1.y));
        o.w = h2u(__floats2half2_rn(v1.z, v1.w));
        *d = o;
    }
}

// ============================================================================
// Phase 1: fp16 m16n8k16 GEMM (unchanged; 355 us measured in R6).
// ============================================================================
constexpr int P1_STG = 4;
constexpr int P1_STAGE_B = 2 * 128 * 32 * 2;   // A 8KB + B 8KB = 16 KB
constexpr int P1_SMEM = P1_STG * P1_STAGE_B;   // 64 KB

__global__ void __launch_bounds__(256, 2) gemm_x_h() {
    extern __shared__ char sm1[];
    const uint32_t sBase = s2u(sm1);

    const int tid = threadIdx.x, lane = tid & 31, warp = tid >> 5;
    const int wm = warp & 3, wn = warp >> 2;
    const bool isInp = (blockIdx.y == 128);
    const int bm = isInp ? 0 : blockIdx.y * 128;
    const int bn = blockIdx.x * 128;
    const __half* Ab = isInp ? g_inp_h : g_act_h + (size_t)bm * KA;
    const __half* Bb = g_wih_h + (size_t)bn * 1024 + (isInp ? 0 : 512);
    float* Cb = isInp ? g_gx_inp : g_gx_act + (size_t)bm * Gd;

    const int r = tid >> 1;
    const int cpair = (tid & 1) * 2;
    const __half* aRow = Ab + (size_t)r * KA;
    const __half* bRow = Bb + (size_t)r * 1024;

    auto loadblk = [&](int kb) {
        if (kb < 16) {
            uint32_t st = sBase + (uint32_t)(kb & 3) * P1_STAGE_B;
            const __half* a = aRow + kb * 32;
            const __half* b = bRow + kb * 32;
            #pragma unroll
            for (int j = 0; j < 2; j++) {
                int c = cpair + j;
                uint32_t off = (uint32_t)(((r >> 3) * 4 + c) * 128)
                             + (uint32_t)((((r & 7) ^ c) * 16));
                cpa16(st + off, a + c * 8);
                cpa16(st + 8192 + off, b + c * 8);
            }
        }
        cpcommit();
    };

    loadblk(0); loadblk(1); loadblk(2);

    float acc[2][8][4];
    #pragma unroll
    for (int i = 0; i < 2; i++)
        #pragma unroll
        for (int j = 0; j < 8; j++)
            #pragma unroll
            for (int k = 0; k < 4; k++) acc[i][j][k] = 0.0f;

    const int g = lane >> 3;
    const int l7 = lane & 7;

    for (int kb = 0; kb < 16; kb++) {
        cpwait<2>(); __syncthreads();
        loadblk(kb + 3);
        const uint32_t stA = sBase + (uint32_t)(kb & 3) * P1_STAGE_B;
        const uint32_t stB = stA + 8192;

        #pragma unroll
        for (int kc = 0; kc < 2; kc++) {
            uint32_t a[2][4];
            #pragma unroll
            for (int tm = 0; tm < 2; tm++) {
                int rt = wm * 4 + tm * 2 + (g & 1);
                int ct = kc * 2 + (g >> 1);
                ldsm4(a[tm][0], a[tm][1], a[tm][2], a[tm][3],
                      stA + (uint32_t)((rt * 4 + ct) * 128 + ((l7 ^ ct) * 16)));
            }
            #pragma unroll
            for (int j = 0; j < 4; j++) {
                int nt = wn * 8 + 2 * j + (g >> 1);
                int ct = kc * 2 + (g & 1);
                uint32_t b0, b1, b2, b3;
                ldsm4(b0, b1, b2, b3,
                      stB + (uint32_t)((nt * 4 + ct) * 128 + ((l7 ^ ct) * 16)));
                mma16(acc[0][2 * j],     a[0], b0, b1);
                mma16(acc[0][2 * j + 1], a[0], b2, b3);
                mma16(acc[1][2 * j],     a[1], b0, b1);
                mma16(acc[1][2 * j + 1], a[1], b2, b3);
            }
        }
    }

    #pragma unroll
    for (int tm = 0; tm < 2; tm++) {
        int rr = wm * 32 + tm * 16 + (lane >> 2);
        #pragma unroll
        for (int tn = 0; tn < 8; tn++) {
            int cc = bn + wn * 64 + tn * 8 + 2 * (lane & 3);
            *(float2*)&Cb[(size_t)rr * Gd + cc] =
                make_float2(acc[tm][tn][0], acc[tm][tn][1]);
            *(float2*)&Cb[(size_t)(rr + 8) * Gd + cc] =
                make_float2(acc[tm][tn][2], acc[tm][tn][3]);
        }
    }
}

// ============================================================================
// Phase 2: persistent LSTM recurrence, 256 threads (R5 math), restructured
// step tail: h-publish (2KB, L2) precedes and is fenced WITHOUT the 16KB
// DRAM out-stores; out-stores execute inside the barrier-wait window.
// 8 staging iterations of 128 cols (32KB slots x4) halve the sync count.
// ============================================================================
constexpr int NTHR = 256;
constexpr int WS_B = 32 * 1024 * 2;             // 64 KB W tiles
constexpr int SLOT2_B = 128 * 128 * 2;          // 32 KB per 128-col slot
constexpr int SMEM2 = WS_B + 4 * SLOT2_B;       // 192 KB

__global__ void __launch_bounds__(NTHR, 1) lstm_seq_kernel(
    const float* __restrict__ h0, const float* __restrict__ c0in,
    const float* __restrict__ Whh, const float* __restrict__ bih,
    const float* __restrict__ bhh, float* __restrict__ out, int out_size)
{
    extern __shared__ char sm2[];
    const uint32_t sW = s2u(sm2);
    const uint32_t sSt = sW + WS_B;

    const int tid = threadIdx.x, lane = tid & 31, warp = tid >> 5;
    const int cta = blockIdx.x;
    const int ub  = cta * 8;
    const int u0  = ub + 2 * (lane & 3);
    const int b0  = warp * 16 + (lane >> 2);

    // --- W_hh slice -> smem fp16, tile-native layout
    for (int i = tid; i < 32 * 128; i += NTHR) {
        int lr = i >> 7;
        int c  = i & 127;
        int gate = lr >> 3, unit = lr & 7;
        const float* src = Whh + (size_t)(gate * Hd + ub + unit) * Hd + c * 8;
        float4 v0 = *(const float4*)src;
        float4 v1 = *(const float4*)(src + 4);
        uint4 o;
        o.x = h2u(__floats2half2_rn(v0.x, v0.y));
        o.y = h2u(__floats2half2_rn(v0.z, v0.w));
        o.z = h2u(__floats2half2_rn(v1.x, v1.y));
        o.w = h2u(__floats2half2_rn(v1.z, v1.w));
        uint32_t off = (uint32_t)((gate * 128 + c) * 128 + ((unit ^ (c & 7)) * 16));
        *(uint4*)(sm2 + off) = o;
    }

    // t-invariant gate term: input-projection + both biases
    float2 gxi[4][2];
    #pragma unroll
    for (int q = 0; q < 4; q++) {
        float bx = bih[q * Hd + u0]     + bhh[q * Hd + u0];
        float by = bih[q * Hd + u0 + 1] + bhh[q * Hd + u0 + 1];
        #pragma unroll
        for (int bs = 0; bs < 2; bs++) {
            int b = b0 + bs * 8;
            float2 v = *(const float2*)&g_gx_inp[(size_t)b * Gd + q * Hd + u0];
            gxi[q][bs] = make_float2(v.x + bx, v.y + by);
        }
    }

    float creg[2][2];
    #pragma unroll
    for (int bs = 0; bs < 2; bs++) {
        int b = b0 + bs * 8;
        creg[bs][0] = c0in[(size_t)b * Hd + u0];
        creg[bs][1] = c0in[(size_t)b * Hd + u0 + 1];
    }

    // initial h (fp16) -> buffer 0
    for (int i = tid; i < Hd / 2; i += NTHR) {
        float2 v = *(const float2*)&h0[(size_t)cta * Hd + 2 * i];
        *(__half2*)&g_hbuf_h[0][cta * Hd + 2 * i] = __floats2half2_rn(v.x, v.y);
    }
    // initial full barrier
    __syncthreads();
    if (tid == 0) {
        __threadfence();
        unsigned old = atomicAdd(&g_bar_count, 1u);
        if ((old + 1u) % gridDim.x == 0u) { __threadfence(); redrel(&g_bar_gen, 1u); }
        while (ldacq(&g_bar_gen) < 1u) { }
        __threadfence();
    }
    __syncthreads();

    // staging + ldmatrix geometry
    const int sr = tid >> 1;                 // staging row 0..127
    const int scb = (tid & 1) * 4;           // 4 chunks of 8 halves
    const int g = lane >> 3, l7 = lane & 7;

    for (int t = 0; t < Lt; t++) {
        const __half* cur = g_hbuf_h[t & 1];
        __half* nxt = g_hbuf_h[(t + 1) & 1];

        float2 gxa[4][2];
        #pragma unroll
        for (int q = 0; q < 4; q++)
            #pragma unroll
            for (int bs = 0; bs < 2; bs++) {
                int b = b0 + bs * 8;
                gxa[q][bs] = *(const float2*)
                    &g_gx_act[((size_t)t * Bt + b) * Gd + q * Hd + u0];
            }

        float acc[4][4];
        #pragma unroll
        for (int q = 0; q < 4; q++)
            #pragma unroll
            for (int k = 0; k < 4; k++) acc[q][k] = 0.0f;

        // stage slot (i&3) with 128 cols = chunks 2i, 2i+1
        auto stage = [&](int i) {
            if (i < 8) {
                uint32_t st = sSt + (uint32_t)(i & 3) * SLOT2_B;
                #pragma unroll
                for (int h = 0; h < 2; h++) {
                    const __half* s = cur + (size_t)sr * Hd + (2 * i + h) * 64;
                    uint32_t base = st + (uint32_t)h * 16384;
                    #pragma unroll
                    for (int j = 0; j < 4; j++) {
                        int c = scb + j;
                        uint32_t off = (uint32_t)(((sr >> 3) * 8 + c) * 128
                                     + (((sr & 7) ^ c) * 16));
                        cpa16(base + off, s + c * 8);
                    }
                }
            }
            cpcommit();
        };

        stage(0); stage(1); stage(2);

        for (int i = 0; i < 8; i++) {
            cpwait<2>(); __syncthreads();
            stage(i + 3);
            #pragma unroll
            for (int h = 0; h < 2; h++) {
                const uint32_t st = sSt + (uint32_t)(i & 3) * SLOT2_B
                                  + (uint32_t)h * 16384;
                const int kbg = 2 * i + h;

                #pragma unroll
                for (int kc = 0; kc < 4; kc++) {
                    uint32_t a[4];
                    {
                        int rt = warp * 2 + (g & 1);
                        int ct = kc * 2 + (g >> 1);
                        ldsm4(a[0], a[1], a[2], a[3],
                              st + (uint32_t)((rt * 8 + ct) * 128 + ((l7 ^ ct) * 16)));
                    }
                    #pragma unroll
                    for (int p = 0; p < 2; p++) {
                        int gate = 2 * p + (g >> 1);
                        int ctg = kbg * 8 + kc * 2 + (g & 1);
                        uint32_t b0r, b1r, b2r, b3r;
                        ldsm4(b0r, b1r, b2r, b3r,
                              sW + (uint32_t)((gate * 128 + ctg) * 128
                                   + ((l7 ^ (ctg & 7)) * 16)));
                        mma16(acc[2 * p],     a, b0r, b1r);
                        mma16(acc[2 * p + 1], a, b2r, b3r);
                    }
                }
            }
        }

        // ---- cell update: gates -> hv/cv in REGISTERS (no out stores yet)
        float hv[2][2], cv[2][2];
        #pragma unroll
        for (int bs = 0; bs < 2; bs++) {
            #pragma unroll
            for (int us = 0; us < 2; us++) {
                int ci = bs * 2 + us;
                float gi = acc[0][ci] + (us ? gxa[0][bs].y : gxa[0][bs].x)
                                      + (us ? gxi[0][bs].y : gxi[0][bs].x);
                float gf = acc[1][ci] + (us ? gxa[1][bs].y : gxa[1][bs].x)
                                      + (us ? gxi[1][bs].y : gxi[1][bs].x);
                float gg = acc[2][ci] + (us ? gxa[2][bs].y : gxa[2][bs].x)
                                      + (us ? gxi[2][bs].y : gxi[2][bs].x);
                float go = acc[3][ci] + (us ? gxa[3][bs].y : gxa[3][bs].x)
                                      + (us ? gxi[3][bs].y : gxi[3][bs].x);
                float cn = sigm(gf) * creg[bs][us] + sigm(gi) * tanhf(gg);
                float hn = sigm(go) * tanhf(cn);
                creg[bs][us] = cn;
                hv[bs][us] = hn; cv[bs][us] = cn;
            }
        }

        if (t + 1 < Lt) {
            // publish h FIRST (2KB per CTA, stays in L2 -> cheap fence)
            #pragma unroll
            for (int bs = 0; bs < 2; bs++) {
                int b = b0 + bs * 8;
                *(__half2*)&nxt[b * Hd + u0] =
                    __floats2half2_rn(hv[bs][0], hv[bs][1]);
            }
            __syncthreads();                 // all h stores issued CTA-wide
            if (tid == 0) {
                __threadfence();             // drains ~2KB of L2 writes only
                unsigned old = atomicAdd(&g_bar_count, 1u);
                if ((old + 1u) % gridDim.x == 0u) {
                    __threadfence();
                    redrel(&g_bar_gen, 1u);
                }
            }
            // out stores ride inside the barrier-wait window
            #pragma unroll
            for (int bs = 0; bs < 2; bs++) {
                int b = b0 + bs * 8;
                size_t ob = (size_t)t * Bt * Hd + (size_t)b * Hd + u0;
                *(float2*)&out[ob] = make_float2(hv[bs][0], hv[bs][1]);
            }
            if (tid == 0) {
                while (ldacq(&g_bar_gen) < (unsigned)(t + 2)) { }
            }
            __syncthreads();
        } else {
            // final step: out + h_n/c_n tail
            #pragma unroll
            for (int bs = 0; bs < 2; bs++) {
                int b = b0 + bs * 8;
                size_t ob = (size_t)t * Bt * Hd + (size_t)b * Hd + u0;
                *(float2*)&out[ob] = make_float2(hv[bs][0], hv[bs][1]);
                size_t HS = (size_t)Lt * Bt * Hd;
                if ((size_t)out_size >= HS + 2 * (size_t)Bt * Hd) {
                    *(float2*)&out[HS + (size_t)b * Hd + u0] =
                        make_float2(hv[bs][0], hv[bs][1]);
                    *(float2*)&out[HS + (size_t)Bt * Hd + (size_t)b * Hd + u0] =
                        make_float2(cv[bs][0], cv[bs][1]);
                }
            }
        }
    }
}

extern "C" void kernel_launch(void* const* d_in, const int* in_sizes, int n_in,
                              void* d_out, int out_size) {
    (void)in_sizes; (void)n_in;
    const float* act = (const float*)d_in[0];
    const float* inp = (const float*)d_in[1];
    const float* h0  = (const float*)d_in[2];
    const float* c0  = (const float*)d_in[3];
    const float* Wih = (const float*)d_in[4];
    const float* Whh = (const float*)d_in[5];
    const float* bih = (const float*)d_in[6];
    const float* bhh = (const float*)d_in[7];
    float* out = (float*)d_out;

    cudaFuncSetAttribute(gemm_x_h,
                         cudaFuncAttributeMaxDynamicSharedMemorySize, P1_SMEM);
    cudaFuncSetAttribute(lstm_seq_kernel,
                         cudaFuncAttributeMaxDynamicSharedMemorySize, SMEM2);

    prep_kernel<<<1024, 256>>>(act, inp, Wih);
    gemm_x_h<<<dim3(32, 129), 256, P1_SMEM>>>();
    lstm_seq_kernel<<<128, NTHR, SMEM2>>>(h0, c0, Whh, bih, bhh, out, out_size);
}

// round 10
// speedup vs baseline: 1.3329x; 1.0800x over previous
#include <cuda_runtime.h>
#include <cuda_fp16.h>
#include <cstdint>

// Problem dims
constexpr int Lt = 128;
constexpr int Bt = 128;
constexpr int Hd = 1024;
constexpr int Gd = 4 * Hd;       // 4096
constexpr int KA = 512;          // K of both phase-1 sub-GEMMs

// Static scratch
__device__ float g_gx_act[(size_t)Lt * Bt * Gd];     // act-side gate projections
__device__ float g_gx_inp[(size_t)Bt * Gd];          // input-side (t-invariant)
__device__ __align__(16) __half g_act_h[(size_t)Lt * Bt * KA];
__device__ __align__(16) __half g_inp_h[(size_t)Bt * KA];
__device__ __align__(16) __half g_wih_h[(size_t)Gd * 1024];
__device__ __align__(16) __half g_hbuf_h[2][Bt * Hd];
__device__ unsigned g_bar_count;
__device__ unsigned g_bar_gen;

// ---------------------------------------------------------------- helpers
__device__ __forceinline__ uint32_t h2u(__half2 v) {
    __half2_raw r = *(__half2_raw*)&v;
    return (uint32_t)r.x | ((uint32_t)r.y << 16);
}
__device__ __forceinline__ void mma16(float* c, const uint32_t* a,
                                      uint32_t b0, uint32_t b1) {
    asm volatile(
        "mma.sync.aligned.m16n8k16.row.col.f32.f16.f16.f32 "
        "{%0,%1,%2,%3},{%4,%5,%6,%7},{%8,%9},{%0,%1,%2,%3};"
        : "+f"(c[0]), "+f"(c[1]), "+f"(c[2]), "+f"(c[3])
        : "r"(a[0]), "r"(a[1]), "r"(a[2]), "r"(a[3]), "r"(b0), "r"(b1));
}
__device__ __forceinline__ void ldsm4(uint32_t& d0, uint32_t& d1,
                                      uint32_t& d2, uint32_t& d3, uint32_t a) {
    asm volatile("ldmatrix.sync.aligned.m8n8.x4.shared.b16 {%0,%1,%2,%3}, [%4];"
                 : "=r"(d0), "=r"(d1), "=r"(d2), "=r"(d3) : "r"(a));
}
__device__ __forceinline__ void cpa16(uint32_t d, const void* s) {
    asm volatile("cp.async.cg.shared.global [%0], [%1], 16;" :: "r"(d), "l"(s));
}
__device__ __forceinline__ void cpcommit() { asm volatile("cp.async.commit_group;"); }
template<int N> __device__ __forceinline__ void cpwait() {
    asm volatile("cp.async.wait_group %0;" :: "n"(N));
}
__device__ __forceinline__ uint32_t s2u(const void* p) {
    return (uint32_t)__cvta_generic_to_shared(p);
}
__device__ __forceinline__ float sigm(float x) { return 1.0f / (1.0f + expf(-x)); }
__device__ __forceinline__ unsigned ldacq(const unsigned* p) {
    unsigned v;
    asm volatile("ld.acquire.gpu.global.u32 %0, [%1];" : "=r"(v) : "l"(p) : "memory");
    return v;
}
__device__ __forceinline__ void redrel(unsigned* p, unsigned v) {
    asm volatile("red.release.gpu.global.add.u32 [%0], %1;" :: "l"(p), "r"(v) : "memory");
}

// ============================================================================
// Prep: fp16-convert act / inp / W_ih; reset sync counters.
// ============================================================================
__global__ void prep_kernel(const float* __restrict__ act,
                            const float* __restrict__ inp,
                            const float* __restrict__ Wih) {
    if (blockIdx.x == 0 && threadIdx.x == 0) { g_bar_count = 0; g_bar_gen = 0; }
    const size_t NW = (size_t)Gd * 1024 / 8;      // 8-elem groups
    const size_t NA = (size_t)Lt * Bt * KA / 8;
    const size_t NI = (size_t)Bt * KA / 8;
    const size_t total = NW + NA + NI;
    for (size_t i = (size_t)blockIdx.x * blockDim.x + threadIdx.x; i < total;
         i += (size_t)gridDim.x * blockDim.x) {
        const float4* s; uint4* d;
        if (i < NW)           { s = (const float4*)Wih + 2 * i;            d = (uint4*)g_wih_h + i; }
        else if (i < NW + NA) { s = (const float4*)act + 2 * (i - NW);     d = (uint4*)g_act_h + (i - NW); }
        else                  { s = (const float4*)inp + 2 * (i - NW - NA); d = (uint4*)g_inp_h + (i - NW - NA); }
        float4 v0 = s[0], v1 = s[1];
        uint4 o;
        o.x = h2u(__floats2half2_rn(v0.x, v0.y));
        o.y = h2u(__floats2half2_rn(v0.z, v0.w));
        o.z = h2u(__floats2half2_rn(v1.x, v1.y));
        o.w = h2u(__floats2half2_rn(v1.z, v1.w));
        *d = o;
    }
}

// ============================================================================
// Phase 1: fp16 m16n8k16 GEMM, BM=BN=128, BK=32, 4-stage cp.async.
// COALESCED staging: each warp instruction reads 8 rows x 64B contiguous
// (full 32B sectors). Smem tile layout / GEMM body unchanged.
// ============================================================================
constexpr int P1_STG = 4;
constexpr int P1_STAGE_B = 2 * 128 * 32 * 2;   // A 8KB + B 8KB = 16 KB
constexpr int P1_SMEM = P1_STG * P1_STAGE_B;   // 64 KB

__global__ void __launch_bounds__(256, 2) gemm_x_h() {
    extern __shared__ char sm1[];
    const uint32_t sBase = s2u(sm1);

    const int tid = threadIdx.x, lane = tid & 31, warp = tid >> 5;
    const int wm = warp & 3, wn = warp >> 2;
    const bool isInp = (blockIdx.y == 128);
    const int bm = isInp ? 0 : blockIdx.y * 128;
    const int bn = blockIdx.x * 128;
    const __half* Ab = isInp ? g_inp_h : g_act_h + (size_t)bm * KA;
    const __half* Bb = g_wih_h + (size_t)bn * 1024 + (isInp ? 0 : 512);
    float* Cb = isInp ? g_gx_inp : g_gx_act + (size_t)bm * Gd;

    // coalesced staging geometry: instr j: rows (warp*2+j)*8 + (lane>>2),
    // chunk c = lane&3 -> warp covers 8 rows x 64B contiguous each.
    const int c4 = lane & 3;
    const int r8 = lane >> 2;

    auto loadblk = [&](int kb) {
        if (kb < 16) {
            uint32_t st = sBase + (uint32_t)(kb & 3) * P1_STAGE_B;
            #pragma unroll
            for (int j = 0; j < 2; j++) {
                int r = (warp * 2 + j) * 8 + r8;
                uint32_t off = (uint32_t)(((r >> 3) * 4 + c4) * 128
                             + (((r & 7) ^ c4) * 16));
                cpa16(st + off, Ab + (size_t)r * KA + kb * 32 + c4 * 8);
                cpa16(st + 8192 + off, Bb + (size_t)r * 1024 + kb * 32 + c4 * 8);
            }
        }
        cpcommit();
    };

    loadblk(0); loadblk(1); loadblk(2);

    float acc[2][8][4];
    #pragma unroll
    for (int i = 0; i < 2; i++)
        #pragma unroll
        for (int j = 0; j < 8; j++)
            #pragma unroll
            for (int k = 0; k < 4; k++) acc[i][j][k] = 0.0f;

    const int g = lane >> 3;
    const int l7 = lane & 7;

    for (int kb = 0; kb < 16; kb++) {
        cpwait<2>(); __syncthreads();
        loadblk(kb + 3);
        const uint32_t stA = sBase + (uint32_t)(kb & 3) * P1_STAGE_B;
        const uint32_t stB = stA + 8192;

        #pragma unroll
        for (int kc = 0; kc < 2; kc++) {
            uint32_t a[2][4];
            #pragma unroll
            for (int tm = 0; tm < 2; tm++) {
                int rt = wm * 4 + tm * 2 + (g & 1);
                int ct = kc * 2 + (g >> 1);
                ldsm4(a[tm][0], a[tm][1], a[tm][2], a[tm][3],
                      stA + (uint32_t)((rt * 4 + ct) * 128 + ((l7 ^ ct) * 16)));
            }
            #pragma unroll
            for (int j = 0; j < 4; j++) {
                int nt = wn * 8 + 2 * j + (g >> 1);
                int ct = kc * 2 + (g & 1);
                uint32_t b0, b1, b2, b3;
                ldsm4(b0, b1, b2, b3,
                      stB + (uint32_t)((nt * 4 + ct) * 128 + ((l7 ^ ct) * 16)));
                mma16(acc[0][2 * j],     a[0], b0, b1);
                mma16(acc[0][2 * j + 1], a[0], b2, b3);
                mma16(acc[1][2 * j],     a[1], b0, b1);
                mma16(acc[1][2 * j + 1], a[1], b2, b3);
            }
        }
    }

    #pragma unroll
    for (int tm = 0; tm < 2; tm++) {
        int rr = wm * 32 + tm * 16 + (lane >> 2);
        #pragma unroll
        for (int tn = 0; tn < 8; tn++) {
            int cc = bn + wn * 64 + tn * 8 + 2 * (lane & 3);
            *(float2*)&Cb[(size_t)rr * Gd + cc] =
                make_float2(acc[tm][tn][0], acc[tm][tn][1]);
            *(float2*)&Cb[(size_t)(rr + 8) * Gd + cc] =
                make_float2(acc[tm][tn][2], acc[tm][tn][3]);
        }
    }
}

// ============================================================================
// Phase 2: persistent LSTM recurrence, 256 threads (R5 math + tail).
// NEW: coalesced h staging (warp reads 2 x 256B contiguous row segments =
// 100% sector efficiency) + per-CTA staggered k-slot order (spreads L2
// slice traffic; only reorders fp32 accumulation).
// ============================================================================
constexpr int NTHR = 256;
constexpr int WS_B = 32 * 1024 * 2;             // 64 KB W tiles
constexpr int SLOT2_B = 128 * 128 * 2;          // 32 KB per 128-col slot
constexpr int SMEM2 = WS_B + 4 * SLOT2_B;       // 192 KB

__device__ __forceinline__ void gbar(unsigned target) {
    __syncthreads();
    if (threadIdx.x == 0) {
        __threadfence();
        unsigned old = atomicAdd(&g_bar_count, 1u);
        if ((old + 1u) % gridDim.x == 0u) {
            __threadfence();
            redrel(&g_bar_gen, 1u);
        } else {
            while (ldacq(&g_bar_gen) < target) { }
        }
        __threadfence();
    }
    __syncthreads();
}

__global__ void __launch_bounds__(NTHR, 1) lstm_seq_kernel(
    const float* __restrict__ h0, const float* __restrict__ c0in,
    const float* __restrict__ Whh, const float* __restrict__ bih,
    const float* __restrict__ bhh, float* __restrict__ out, int out_size)
{
    extern __shared__ char sm2[];
    const uint32_t sW = s2u(sm2);
    const uint32_t sSt = sW + WS_B;

    const int tid = threadIdx.x, lane = tid & 31, warp = tid >> 5;
    const int cta = blockIdx.x;
    const int ub  = cta * 8;
    const int u0  = ub + 2 * (lane & 3);
    const int b0  = warp * 16 + (lane >> 2);
    const int stag = cta & 7;                // per-CTA k-slot stagger

    // --- W_hh slice -> smem fp16, tile-native layout
    for (int i = tid; i < 32 * 128; i += NTHR) {
        int lr = i >> 7;
        int c  = i & 127;
        int gate = lr >> 3, unit = lr & 7;
        const float* src = Whh + (size_t)(gate * Hd + ub + unit) * Hd + c * 8;
        float4 v0 = *(const float4*)src;
        float4 v1 = *(const float4*)(src + 4);
        uint4 o;
        o.x = h2u(__floats2half2_rn(v0.x, v0.y));
        o.y = h2u(__floats2half2_rn(v0.z, v0.w));
        o.z = h2u(__floats2half2_rn(v1.x, v1.y));
        o.w = h2u(__floats2half2_rn(v1.z, v1.w));
        uint32_t off = (uint32_t)((gate * 128 + c) * 128 + ((unit ^ (c & 7)) * 16));
        *(uint4*)(sm2 + off) = o;
    }

    // t-invariant gate term: input-projection + both biases
    float2 gxi[4][2];
    #pragma unroll
    for (int q = 0; q < 4; q++) {
        float bx = bih[q * Hd + u0]     + bhh[q * Hd + u0];
        float by = bih[q * Hd + u0 + 1] + bhh[q * Hd + u0 + 1];
        #pragma unroll
        for (int bs = 0; bs < 2; bs++) {
            int b = b0 + bs * 8;
            float2 v = *(const float2*)&g_gx_inp[(size_t)b * Gd + q * Hd + u0];
            gxi[q][bs] = make_float2(v.x + bx, v.y + by);
        }
    }

    float creg[2][2];
    #pragma unroll
    for (int bs = 0; bs < 2; bs++) {
        int b = b0 + bs * 8;
        creg[bs][0] = c0in[(size_t)b * Hd + u0];
        creg[bs][1] = c0in[(size_t)b * Hd + u0 + 1];
    }

    // initial h (fp16) -> buffer 0
    for (int i = tid; i < Hd / 2; i += NTHR) {
        float2 v = *(const float2*)&h0[(size_t)cta * Hd + 2 * i];
        *(__half2*)&g_hbuf_h[0][cta * Hd + 2 * i] = __floats2half2_rn(v.x, v.y);
    }
    gbar(1);

    // coalesced staging geometry: instr j: row = (warp*8+j)*2 + (lane>>4),
    // chunk c = lane&15  -> warp reads two contiguous 256B row segments.
    const int srow_half = lane >> 4;         // 0/1: which of the row pair
    const int sc = lane & 15;                // 16B chunk within 256B segment
    const int shalf = sc >> 3, scc = sc & 7; // smem half + chunk-in-half
    const int g = lane >> 3, l7 = lane & 7;

    for (int t = 0; t < Lt; t++) {
        const __half* cur = g_hbuf_h[t & 1];
        __half* nxt = g_hbuf_h[(t + 1) & 1];

        float2 gxa[4][2];
        #pragma unroll
        for (int q = 0; q < 4; q++)
            #pragma unroll
            for (int bs = 0; bs < 2; bs++) {
                int b = b0 + bs * 8;
                gxa[q][bs] = *(const float2*)
                    &g_gx_act[((size_t)t * Bt + b) * Gd + q * Hd + u0];
            }

        float acc[4][4];
        #pragma unroll
        for (int q = 0; q < 4; q++)
            #pragma unroll
            for (int k = 0; k < 4; k++) acc[q][k] = 0.0f;

        // stage slot (i&3) with k-slot ks = (i+stag)&7  (128 cols)
        auto stage = [&](int i) {
            if (i < 8) {
                int ks = (i + stag) & 7;
                uint32_t st = sSt + (uint32_t)(i & 3) * SLOT2_B;
                #pragma unroll
                for (int j = 0; j < 8; j++) {
                    int r = (warp * 8 + j) * 2 + srow_half;
                    uint32_t off = (uint32_t)(shalf * 16384
                                 + ((r >> 3) * 8 + scc) * 128
                                 + (((r & 7) ^ scc) * 16));
                    cpa16(st + off, cur + (size_t)r * Hd + ks * 128 + sc * 8);
                }
            }
            cpcommit();
        };

        stage(0); stage(1); stage(2);

        for (int i = 0; i < 8; i++) {
            cpwait<2>(); __syncthreads();
            stage(i + 3);
            const int ks = (i + stag) & 7;
            #pragma unroll
            for (int h = 0; h < 2; h++) {
                const uint32_t st = sSt + (uint32_t)(i & 3) * SLOT2_B
                                  + (uint32_t)h * 16384;
                const int kbg = 2 * ks + h;

                #pragma unroll
                for (int kc = 0; kc < 4; kc++) {
                    uint32_t a[4];
                    {
                        int rt = warp * 2 + (g & 1);
                        int ct = kc * 2 + (g >> 1);
                        ldsm4(a[0], a[1], a[2], a[3],
                              st + (uint32_t)((rt * 8 + ct) * 128 + ((l7 ^ ct) * 16)));
                    }
                    #pragma unroll
                    for (int p = 0; p < 2; p++) {
                        int gate = 2 * p + (g >> 1);
                        int ctg = kbg * 8 + kc * 2 + (g & 1);
                        uint32_t b0r, b1r, b2r, b3r;
                        ldsm4(b0r, b1r, b2r, b3r,
                              sW + (uint32_t)((gate * 128 + ctg) * 128
                                   + ((l7 ^ (ctg & 7)) * 16)));
                        mma16(acc[2 * p],     a, b0r, b1r);
                        mma16(acc[2 * p + 1], a, b2r, b3r);
                    }
                }
            }
        }

        // cell update (R5 tail: stores inline, then barrier)
        #pragma unroll
        for (int bs = 0; bs < 2; bs++) {
            int b = b0 + bs * 8;
            float hv[2], cv[2];
            #pragma unroll
            for (int us = 0; us < 2; us++) {
                int ci = bs * 2 + us;
                float gi = acc[0][ci] + (us ? gxa[0][bs].y : gxa[0][bs].x)
                                      + (us ? gxi[0][bs].y : gxi[0][bs].x);
                float gf = acc[1][ci] + (us ? gxa[1][bs].y : gxa[1][bs].x)
                                      + (us ? gxi[1][bs].y : gxi[1][bs].x);
                float gg = acc[2][ci] + (us ? gxa[2][bs].y : gxa[2][bs].x)
                                      + (us ? gxi[2][bs].y : gxi[2][bs].x);
                float go = acc[3][ci] + (us ? gxa[3][bs].y : gxa[3][bs].x)
                                      + (us ? gxi[3][bs].y : gxi[3][bs].x);
                float cn = sigm(gf) * creg[bs][us] + sigm(gi) * tanhf(gg);
                float hn = sigm(go) * tanhf(cn);
                creg[bs][us] = cn;
                hv[us] = hn; cv[us] = cn;
            }
            size_t ob = (size_t)t * Bt * Hd + (size_t)b * Hd + u0;
            *(float2*)&out[ob] = make_float2(hv[0], hv[1]);
            if (t + 1 < Lt) {
                *(__half2*)&nxt[b * Hd + u0] = __floats2half2_rn(hv[0], hv[1]);
            } else {
                size_t HS = (size_t)Lt * Bt * Hd;
                if ((size_t)out_size >= HS + 2 * (size_t)Bt * Hd) {
                    *(float2*)&out[HS + (size_t)b * Hd + u0] =
                        make_float2(hv[0], hv[1]);
                    *(float2*)&out[HS + (size_t)Bt * Hd + (size_t)b * Hd + u0] =
                        make_float2(cv[0], cv[1]);
                }
            }
        }
        if (t + 1 < Lt) gbar((unsigned)(t + 2));
    }
}

extern "C" void kernel_launch(void* const* d_in, const int* in_sizes, int n_in,
                              void* d_out, int out_size) {
    (void)in_sizes; (void)n_in;
    const float* act = (const float*)d_in[0];
    const float* inp = (const float*)d_in[1];
    const float* h0  = (const float*)d_in[2];
    const float* c0  = (const float*)d_in[3];
    const float* Wih = (const float*)d_in[4];
    const float* Whh = (const float*)d_in[5];
    const float* bih = (const float*)d_in[6];
    const float* bhh = (const float*)d_in[7];
    float* out = (float*)d_out;

    cudaFuncSetAttribute(gemm_x_h,
                         cudaFuncAttributeMaxDynamicSharedMemorySize, P1_SMEM);
    cudaFuncSetAttribute(lstm_seq_kernel,
                         cudaFuncAttributeMaxDynamicSharedMemorySize, SMEM2);

    prep_kernel<<<1024, 256>>>(act, inp, Wih);
    gemm_x_h<<<dim3(32, 129), 256, P1_SMEM>>>();
    lstm_seq_kernel<<<128, NTHR, SMEM2>>>(h0, c0, Whh, bih, bhh, out, out_size);
}